// round 16
// baseline (speedup 1.0000x reference)
#include <cuda_runtime.h>
#include <math.h>
#include <stdint.h>

#define MAXDISP      192
#define ROW_FLOATS   MAXDISP
#define ROW_BYTES    (ROW_FLOATS * 4)              // 768
#define CHUNK_ROWS   16
#define NCHUNK       4                             // ring slots
#define CHUNK_FLOATS (CHUNK_ROWS * ROW_FLOATS)     // 3072
#define CHUNK_BYTES  (CHUNK_FLOATS * 4)            // 12288
#define NWARPS_CONS  8
#define NTHREADS     (32 * (NWARPS_CONS + 1))      // 288: 8 consumers + 1 producer
#define GRID_CTAS    592                           // 4 per SM x 148 SMs, one wave

// Bijective monotone map: float bits -> uint32, uint compare == float compare.
__device__ __forceinline__ unsigned f2k(float f) {
    unsigned b = __float_as_uint(f);
    return b ^ (unsigned)(((int)b >> 31) | 0x80000000);
}
__device__ __forceinline__ float k2f(unsigned k) {
    unsigned t = (unsigned)((int)k >> 31);
    return __uint_as_float(k ^ (~t | 0x80000000u));
}
__device__ __forceinline__ unsigned decode_col(unsigned b0, unsigned s) {
    return b0 + (s & 1u) + ((s >> 1) << 6);
}

#define MBAR_INIT(addr, cnt) \
    asm volatile("mbarrier.init.shared.b64 [%0], %1;" :: "r"(addr), "r"(cnt) : "memory")
#define MBAR_ARRIVE(addr) \
    asm volatile("mbarrier.arrive.shared.b64 _, [%0];" :: "r"(addr) : "memory")
#define MBAR_WAIT(addr, ph) do {                                              \
    asm volatile(                                                             \
        "{\n\t.reg .pred P1;\n\t"                                             \
        "WAIT_LOOP_%=:\n\t"                                                   \
        "mbarrier.try_wait.parity.acquire.cta.shared::cta.b64 P1, [%0], %1, 0x989680;\n\t" \
        "@P1 bra.uni WAIT_DONE_%=;\n\t"                                       \
        "bra.uni WAIT_LOOP_%=;\n\t"                                           \
        "WAIT_DONE_%=:\n\t}"                                                  \
        :: "r"(addr), "r"(ph) : "memory");                                    \
} while (0)

struct RowRes { unsigned ka, kb, i1, i2; };

// Exact top-2 of one row (6 values/lane) + exact warp top-2 with
// lowest-column tie-break. All tie paths keep the earlier column.
__device__ __forceinline__ RowRes row_top2(const float2* dd, unsigned b0) {
    const float x0 = dd[0].x, x1 = dd[0].y;
    const float x2 = dd[1].x, x3 = dd[1].y;
    const float x4 = dd[2].x, x5 = dd[2].y;

    const bool g0 = x1 > x0;
    const float h0 = fmaxf(x0, x1), l0 = fminf(x0, x1);
    const unsigned s0h = g0 ? 1u : 0u, s0l = 1u - s0h;

    const bool g1 = x3 > x2;
    const float h1 = fmaxf(x2, x3), l1 = fminf(x2, x3);
    const unsigned s1h = g1 ? 3u : 2u, s1l = 5u - s1h;

    const bool g2 = x5 > x4;
    const float h2 = fmaxf(x4, x5), l2 = fminf(x4, x5);
    const unsigned s2h = g2 ? 5u : 4u, s2l = 9u - s2h;

    float v1, v2; unsigned c1, c2;
    {
        const bool m = h1 > h0;
        v1 = fmaxf(h0, h1);
        c1 = m ? s1h : s0h;
        const float    sa = m ? h0  : l0;
        const unsigned ca = m ? s0h : s0l;
        const float    sb = m ? l1  : h1;
        const unsigned cb = m ? s1l : s1h;
        const bool h = sb > sa;
        v2 = fmaxf(sa, sb);
        c2 = h ? cb : ca;
    }
    {
        const bool m = h2 > v1;
        const float    nv1 = fmaxf(v1, h2);
        const unsigned nc1 = m ? s2h : c1;
        const float    sa = m ? v1 : v2;
        const unsigned ca = m ? c1 : c2;
        const float    sb = m ? l2  : h2;
        const unsigned cb = m ? s2l : s2h;
        const bool h = sb > sa;
        v2 = fmaxf(sa, sb);
        c2 = h ? cb : ca;
        v1 = nv1; c1 = nc1;
    }

    const unsigned k1 = f2k(v1);
    const unsigned t1 = __reduce_max_sync(0xFFFFFFFFu, k1);
    const unsigned col1 = decode_col(b0, c1);
    const unsigned gi1 = __reduce_min_sync(0xFFFFFFFFu,
                                           (k1 == t1) ? col1 : 0xFFFFu);

    const bool own = (col1 == gi1);
    const float    cnd = own ? v2 : v1;
    const unsigned cc  = own ? c2 : c1;
    const unsigned k2 = f2k(cnd);
    const unsigned t2 = __reduce_max_sync(0xFFFFFFFFu, k2);
    const unsigned col2 = decode_col(b0, cc);
    const unsigned gi2 = __reduce_min_sync(0xFFFFFFFFu,
                                           (k2 == t2) ? col2 : 0xFFFFu);

    RowRes res; res.ka = t1; res.kb = t2; res.i1 = gi1; res.i2 = gi2;
    return res;
}

__global__ __launch_bounds__(NTHREADS)
void disp_reg_kernel(const float* __restrict__ cost,
                     float* __restrict__ out,
                     int nrows)
{
    extern __shared__ float sbuf[];            // NCHUNK x 12KB ring
    __shared__ uint64_t full_b[NCHUNK], empty_b[NCHUNK];

    const int tid  = threadIdx.x;
    const int warp = tid >> 5;
    const int lane = tid & 31;

    const int NC_TOT = (nrows + CHUNK_ROWS - 1) / CHUNK_ROWS;
    const int span   = (NC_TOT + (int)gridDim.x - 1) / (int)gridDim.x;
    const int c0     = (int)blockIdx.x * span;
    int ncl = NC_TOT - c0;
    if (ncl > span) ncl = span;
    if (ncl < 0)    ncl = 0;

    if (tid == 0) {
#pragma unroll
        for (int s = 0; s < NCHUNK; s++) {
            MBAR_INIT((unsigned)__cvta_generic_to_shared(&full_b[s]), 1u);
            MBAR_INIT((unsigned)__cvta_generic_to_shared(&empty_b[s]),
                      (unsigned)NWARPS_CONS);
        }
        asm volatile("fence.proxy.async.shared::cta;" ::: "memory");
    }
    __syncthreads();

    if (warp == NWARPS_CONS) {
        // -------- Producer: keep the TMA stream continuously fed. --------
        if (lane == 0) {
            int slot = 0, eph = 1;                 // parity trick: first
            for (int i = 0; i < ncl; i++) {        // NCHUNK waits pass free
                const unsigned eb = (unsigned)__cvta_generic_to_shared(&empty_b[slot]);
                MBAR_WAIT(eb, eph);

                const long long first = (long long)(c0 + i) * CHUNK_ROWS;
                const long long rem   = (long long)nrows - first;
                const unsigned bytes =
                    (unsigned)((rem * ROW_BYTES < CHUNK_BYTES)
                                   ? rem * ROW_BYTES : CHUNK_BYTES);
                const unsigned fb  = (unsigned)__cvta_generic_to_shared(&full_b[slot]);
                const unsigned dst = (unsigned)__cvta_generic_to_shared(
                                         sbuf + slot * CHUNK_FLOATS);
                const float* src = cost + first * ROW_FLOATS;
                asm volatile("mbarrier.arrive.expect_tx.shared.b64 _, [%0], %1;"
                             :: "r"(fb), "r"(bytes) : "memory");
                asm volatile(
                    "cp.async.bulk.shared::cta.global.mbarrier::complete_tx::bytes"
                    " [%0], [%1], %2, [%3];"
                    :: "r"(dst), "l"(src), "r"(bytes), "r"(fb) : "memory");

                if (++slot == NCHUNK) { slot = 0; eph ^= 1; }
            }
        }
    } else {
        // -------- Consumers: warp w owns rows {2w, 2w+1} of every chunk. --
        const unsigned b0 = (unsigned)(lane * 2);
        int slot = 0, fph = 0;
        for (int i = 0; i < ncl; i++) {
            const unsigned fb = (unsigned)__cvta_generic_to_shared(&full_b[slot]);
            MBAR_WAIT(fb, fph);

            const int rowA = (c0 + i) * CHUNK_ROWS + warp * 2;
            const float* chunk =
                sbuf + slot * CHUNK_FLOATS + (warp * 2) * ROW_FLOATS;

            unsigned rka = 0, rkb = 0, ri1 = 0, ri2 = 0;
#pragma unroll
            for (int r = 0; r < 2; r++) {
                float2 d[3];
#pragma unroll
                for (int k = 0; k < 3; k++)
                    d[k] = *(const float2*)(chunk + r * ROW_FLOATS
                                            + b0 + 64 * k);
                const RowRes res = row_top2(d, b0);
                if (lane == r) { rka = res.ka; rkb = res.kb;
                                 ri1 = res.i1; ri2 = res.i2; }
            }

            // All lanes done reading this slot before releasing it.
            __syncwarp();
            if (lane == 0) {
                const unsigned eb =
                    (unsigned)__cvta_generic_to_shared(&empty_b[slot]);
                MBAR_ARRIVE(eb);
            }

            if (lane < 2 && (rowA + lane) < nrows) {
                const float va = k2f(rka);
                const float vb = k2f(rkb);
                const float p = 1.0f / (1.0f + __expf(vb - va));
                out[rowA + lane] = (float)ri1 * p + (float)ri2 * (1.0f - p);
            }

            if (++slot == NCHUNK) { slot = 0; fph ^= 1; }
        }
    }
}

extern "C" void kernel_launch(void* const* d_in, const int* in_sizes, int n_in,
                              void* d_out, int out_size)
{
    const float* cost = (const float*)d_in[0];
    float* out = (float*)d_out;

    const int nrows = in_sizes[0] / MAXDISP;   // 4 * 131072 = 524288
    const int smem = NCHUNK * CHUNK_BYTES;     // 49152 B dynamic

    static bool attr_done = false;
    if (!attr_done) {
        cudaFuncSetAttribute(disp_reg_kernel,
                             cudaFuncAttributeMaxDynamicSharedMemorySize,
                             smem + 1024);
        attr_done = true;
    }

    disp_reg_kernel<<<GRID_CTAS, NTHREADS, smem>>>(cost, out, nrows);
}

// round 17
// speedup vs baseline: 1.1733x; 1.1733x over previous
#include <cuda_runtime.h>
#include <math.h>

#define MAXDISP 192
#define BATCH 2            // rows per load burst (6 x LDG.64)
#define NBAT  2            // batches per warp
#define RPW   (BATCH * NBAT)   // 4 rows per warp

// Bijective monotone map: float bits -> uint32, uint compare == float compare.
__device__ __forceinline__ unsigned f2k(float f) {
    unsigned b = __float_as_uint(f);
    return b ^ (unsigned)(((int)b >> 31) | 0x80000000);
}
__device__ __forceinline__ float k2f(unsigned k) {
    unsigned t = (unsigned)((int)k >> 31);         // all-ones if orig positive
    return __uint_as_float(k ^ (~t | 0x80000000u));
}

// slot code s in 0..5 -> column = b0 + (s&1) + (s>>1)*64
__device__ __forceinline__ unsigned decode_col(unsigned b0, unsigned s) {
    return b0 + (s & 1u) + ((s >> 1) << 6);
}

struct RowRes { unsigned ka, kb, i1, i2; };

// Exact top-2 of one row slice (6 values) + exact warp top-2 with
// lowest-column tie-break. All tie paths keep the earlier column.
__device__ __forceinline__ RowRes row_top2(const float2* dd, unsigned b0) {
    const float x0 = dd[0].x, x1 = dd[0].y;
    const float x2 = dd[1].x, x3 = dd[1].y;
    const float x4 = dd[2].x, x5 = dd[2].y;

    // Column-ordered pairs; strict '>' -> ties keep earlier slot.
    const bool g0 = x1 > x0;
    const float h0 = fmaxf(x0, x1), l0 = fminf(x0, x1);
    const unsigned s0h = g0 ? 1u : 0u, s0l = 1u - s0h;

    const bool g1 = x3 > x2;
    const float h1 = fmaxf(x2, x3), l1 = fminf(x2, x3);
    const unsigned s1h = g1 ? 3u : 2u, s1l = 5u - s1h;

    const bool g2 = x5 > x4;
    const float h2 = fmaxf(x4, x5), l2 = fminf(x4, x5);
    const unsigned s2h = g2 ? 5u : 4u, s2l = 9u - s2h;

    // merge(pair0, pair1): A = earlier columns; ties -> A side.
    float v1, v2; unsigned c1, c2;
    {
        const bool m = h1 > h0;
        v1 = fmaxf(h0, h1);
        c1 = m ? s1h : s0h;
        const float    sa = m ? h0  : l0;
        const unsigned ca = m ? s0h : s0l;
        const float    sb = m ? l1  : h1;
        const unsigned cb = m ? s1l : s1h;
        const bool h = sb > sa;
        v2 = fmaxf(sa, sb);
        c2 = h ? cb : ca;
    }
    // merge(M, pair2)
    {
        const bool m = h2 > v1;
        const float    nv1 = fmaxf(v1, h2);
        const unsigned nc1 = m ? s2h : c1;
        const float    sa = m ? v1 : v2;
        const unsigned ca = m ? c1 : c2;
        const float    sb = m ? l2  : h2;
        const unsigned cb = m ? s2l : s2h;
        const bool h = sb > sa;
        v2 = fmaxf(sa, sb);
        c2 = h ? cb : ca;
        v1 = nv1; c1 = nc1;
    }

    // Warp top-1 (exact value via bijective key).
    const unsigned k1 = f2k(v1);
    const unsigned t1 = __reduce_max_sync(0xFFFFFFFFu, k1);
    const unsigned col1 = decode_col(b0, c1);
    const unsigned gi1 = __reduce_min_sync(0xFFFFFFFFu,
                                           (k1 == t1) ? col1 : 0xFFFFu);

    // Columns are unique across lanes, so col1==gi1 identifies the single
    // owner; tied duplicate lanes keep v1 so exact ties reach rank 2.
    const bool own = (col1 == gi1);
    const float    cnd = own ? v2 : v1;
    const unsigned cc  = own ? c2 : c1;
    const unsigned k2 = f2k(cnd);
    const unsigned t2 = __reduce_max_sync(0xFFFFFFFFu, k2);
    const unsigned col2 = decode_col(b0, cc);
    const unsigned gi2 = __reduce_min_sync(0xFFFFFFFFu,
                                           (k2 == t2) ? col2 : 0xFFFFu);

    RowRes res; res.ka = t1; res.kb = t2; res.i1 = gi1; res.i2 = gi2;
    return res;
}

__global__ __launch_bounds__(256, 6)
void disp_reg_kernel(const float* __restrict__ cost,
                     float* __restrict__ out,
                     int nrows)
{
    const int warp = (blockIdx.x * blockDim.x + threadIdx.x) >> 5;
    const int lane = threadIdx.x & 31;
    const int row0 = warp * RPW;
    if (row0 >= nrows) return;

    const float* base = cost + (size_t)row0 * MAXDISP;
    const unsigned b0 = (unsigned)(lane * 2);

    // Per-row results stashed in lane r's registers (as keys).
    unsigned rka = 0, rkb = 0, ri1 = 0, ri2 = 0;

    // Two batches of 2 rows: 6 front-batched LDG.64 per burst.
    // __ldcs: single-touch stream, evict-first in L2.
#pragma unroll
    for (int bat = 0; bat < NBAT; bat++) {
        float2 d[BATCH][3];
#pragma unroll
        for (int r = 0; r < BATCH; r++) {
#pragma unroll
            for (int k = 0; k < 3; k++) {
                d[r][k] = __ldcs((const float2*)(base
                              + (bat * BATCH + r) * MAXDISP + b0 + 64 * k));
            }
        }
#pragma unroll
        for (int r = 0; r < BATCH; r++) {
            const RowRes res = row_top2(d[r], b0);
            const int rr = bat * BATCH + r;
            if (lane == rr) { rka = res.ka; rkb = res.kb;
                              ri1 = res.i1; ri2 = res.i2; }
        }
    }

    // Consolidated epilogue: lanes 0..RPW-1 finalize their rows
    // (RPW parallel exp's, one coalesced 16B store per warp).
    if (lane < RPW && (row0 + lane) < nrows) {
        const float va = k2f(rka);
        const float vb = k2f(rkb);
        const float p = 1.0f / (1.0f + __expf(vb - va));
        out[row0 + lane] = (float)ri1 * p + (float)ri2 * (1.0f - p);
    }
}

extern "C" void kernel_launch(void* const* d_in, const int* in_sizes, int n_in,
                              void* d_out, int out_size)
{
    const float* cost = (const float*)d_in[0];
    float* out = (float*)d_out;

    const int nrows = in_sizes[0] / MAXDISP;   // 4 * 131072 = 524288

    const int threads = 256;                   // 8 warps/block, 32 rows/block
    const int rows_per_block = (threads / 32) * RPW;
    const int blocks = (nrows + rows_per_block - 1) / rows_per_block;

    disp_reg_kernel<<<blocks, threads>>>(cost, out, nrows);
}